// round 7
// baseline (speedup 1.0000x reference)
#include <cuda_runtime.h>
#include <cuda_bf16.h>
#include <math.h>

// Problem constants
constexpr int S = 4;
constexpr int T = 512;
constexpr int B = 16;
constexpr int D = 512;

constexpr int RPAIRS = T / 2;          // 256 t-row pairs per batch
constexpr int CPB    = 18;             // block slots per batch
constexpr int NBLOCKS = CPB * B;       // 288 = one wave at occ 2
constexpr int NACC   = 24;             // 16 dots (sp*4+sg) + 4 pred norms + 4 gt norms

using u64 = unsigned long long;

// Deterministic scratch: per-(batch, block-slot) partial accumulators.
__device__ float g_part[B][CPB][NACC];
__device__ int   g_done = 0;

__device__ __forceinline__ void fma2(u64& acc, u64 a, u64 b) {
    asm("fma.rn.f32x2 %0, %1, %2, %0;" : "+l"(acc) : "l"(a), "l"(b));
}
__device__ __forceinline__ u64 pack2(float lo, float hi) {
    u64 v;
    asm("mov.b64 %0, {%1, %2};" : "=l"(v) : "f"(lo), "f"(hi));
    return v;
}
__device__ __forceinline__ float unpack_sum(u64 v) {
    float lo, hi;
    asm("mov.b64 {%0, %1}, %2;" : "=f"(lo), "=f"(hi) : "l"(v));
    return lo + hi;
}

// Accumulate one row-set (4 pred float4 + 4 gt float4) into the 24 packed accs.
__device__ __forceinline__ void accum_rows(u64* acc, const float4* p, const float4* g) {
    u64 px[4][2], gx[4][2];
#pragma unroll
    for (int s = 0; s < 4; ++s) {
        px[s][0] = pack2(p[s].x, p[s].y);
        px[s][1] = pack2(p[s].z, p[s].w);
        gx[s][0] = pack2(g[s].x, g[s].y);
        gx[s][1] = pack2(g[s].z, g[s].w);
    }
#pragma unroll
    for (int sp = 0; sp < 4; ++sp) {
        fma2(acc[16 + sp], px[sp][0], px[sp][0]);   // pred norm
        fma2(acc[16 + sp], px[sp][1], px[sp][1]);
        fma2(acc[20 + sp], gx[sp][0], gx[sp][0]);   // gt norm
        fma2(acc[20 + sp], gx[sp][1], gx[sp][1]);
#pragma unroll
        for (int sg = 0; sg < 4; ++sg) {
            fma2(acc[sp * 4 + sg], px[sp][0], gx[sg][0]);
            fma2(acc[sp * 4 + sg], px[sp][1], gx[sg][1]);
        }
    }
}

// ---------------------------------------------------------------------------
// Fused single-wave kernel, 2x-unrolled mainloop (16 LDG.128 in flight/warp).
// Block (cx, b): batch b, row pairs rp = cx, cx+18, ... (< 256), two at a time.
// Thread layout: lane128 = tid & 127 spans D via float4; tid>>7 = row in pair.
// ---------------------------------------------------------------------------
__global__ __launch_bounds__(256, 2) void minloss_fused(
    const float* __restrict__ preds,   // [S, T, B, D]
    const float* __restrict__ gts,     // [S, B, T, D]
    float* __restrict__ out)
{
    const int b    = blockIdx.y;
    const int cx   = blockIdx.x;
    const int tid  = threadIdx.x;
    const int lane128 = tid & 127;
    const int trow    = tid >> 7;      // 0 or 1: row within the pair

    // Per-source base pointers (float4 granularity), t baked in via offsets.
    const float4* pbase[S];
    const float4* gbase[S];
#pragma unroll
    for (int s = 0; s < 4; ++s) {
        pbase[s] = (const float4*)preds + (size_t)s * T * B * (D / 4) + b * (D / 4) + lane128 + (size_t)trow * B * (D / 4);
        gbase[s] = (const float4*)gts   + ((size_t)s * B + b) * T * (D / 4) + lane128 + (size_t)trow * (D / 4);
    }
    constexpr int PT = B * D / 4;      // float4 stride per t in preds (2048)
    constexpr int GT = D / 4;          // float4 stride per t in gts   (128)

    u64 acc[NACC];
#pragma unroll
    for (int i = 0; i < NACC; ++i) acc[i] = 0ull;

    int rp = cx;
    // Unrolled x2: batch 16 independent LDG.128 before any FMA.
    while (rp + CPB < RPAIRS) {
        const int tA = 2 * rp;
        const int tB = 2 * (rp + CPB);
        float4 pA[4], gA[4], pB[4], gB[4];
#pragma unroll
        for (int s = 0; s < 4; ++s) {
            pA[s] = __ldcs(pbase[s] + (size_t)tA * PT);
            gA[s] = __ldcs(gbase[s] + (size_t)tA * GT);
            pB[s] = __ldcs(pbase[s] + (size_t)tB * PT);
            gB[s] = __ldcs(gbase[s] + (size_t)tB * GT);
        }
        accum_rows(acc, pA, gA);
        accum_rows(acc, pB, gB);
        rp += 2 * CPB;
    }
    if (rp < RPAIRS) {                 // tail (one row-set)
        const int tA = 2 * rp;
        float4 pA[4], gA[4];
#pragma unroll
        for (int s = 0; s < 4; ++s) {
            pA[s] = __ldcs(pbase[s] + (size_t)tA * PT);
            gA[s] = __ldcs(gbase[s] + (size_t)tA * GT);
        }
        accum_rows(acc, pA, gA);
    }

    // Unpack + warp reduction
    float vals[NACC];
#pragma unroll
    for (int i = 0; i < NACC; ++i) {
        vals[i] = unpack_sum(acc[i]);
#pragma unroll
        for (int off = 16; off > 0; off >>= 1)
            vals[i] += __shfl_down_sync(0xffffffffu, vals[i], off);
    }

    __shared__ float sacc[8][NACC];
    const int warp = tid >> 5;
    const int lane = tid & 31;
    if (lane == 0) {
#pragma unroll
        for (int i = 0; i < NACC; ++i) sacc[warp][i] = vals[i];
    }
    __syncthreads();

    if (tid < NACC) {
        float a = 0.0f;
#pragma unroll
        for (int w = 0; w < 8; ++w) a += sacc[w][tid];
        g_part[b][cx][tid] = a;                       // deterministic overwrite
    }

    // ---- last-block ticket ----
    __threadfence();
    __syncthreads();
    __shared__ int s_last;
    if (tid == 0) {
        int ticket = atomicAdd(&g_done, 1);
        s_last = (ticket == NBLOCKS - 1);
    }
    __syncthreads();
    if (!s_last) return;

    // =========================== Phase B (last block) ===========================
    __threadfence();                                  // acquire

    __shared__ float s_final[B][NACC];

    // 8 warps; warp w reduces batches 2w and 2w+1. Lanes 0..23 own one acc idx.
#pragma unroll
    for (int k = 0; k < 2; ++k) {
        const int bb = warp * 2 + k;
        if (lane < NACC) {
            float a = 0.0f;
#pragma unroll
            for (int cc = 0; cc < CPB; ++cc)
                a += __ldcg(&g_part[bb][cc][lane]);   // L2, bypass stale L1
            s_final[bb][lane] = a;
        }
    }
    __syncthreads();

    __shared__ float batch_total[B];

    // 16 threads: one greedy matching per batch (first-occurrence argmin order).
    if (tid < B) {
        const float* a = s_final[tid];
        float dist[16];
#pragma unroll
        for (int sp = 0; sp < 4; ++sp)
#pragma unroll
            for (int sg = 0; sg < 4; ++sg) {
                float d2 = a[16 + sp] + a[20 + sg] - 2.0f * a[sp * 4 + sg];
                dist[sp * 4 + sg] = sqrtf(fmaxf(d2, 0.0f));
            }

        const float INF = __int_as_float(0x7f800000);
        float total = 0.0f;
#pragma unroll
        for (int it = 0; it < 4; ++it) {
            int   m    = 0;
            float best = dist[0];
#pragma unroll
            for (int k = 1; k < 16; ++k)
                if (dist[k] < best) { best = dist[k]; m = k; }
            total += best;
            const int r = m >> 2, cc = m & 3;
#pragma unroll
            for (int k = 0; k < 4; ++k) {
                dist[r * 4 + k]  = INF;
                dist[k * 4 + cc] = INF;
            }
        }
        batch_total[tid] = total;
    }
    __syncthreads();

    if (tid == 0) {
        float s = 0.0f;
#pragma unroll
        for (int bb = 0; bb < B; ++bb) s += batch_total[bb];
        out[0] = s;
        g_done = 0;                                   // reset for next graph replay
    }
}

extern "C" void kernel_launch(void* const* d_in, const int* in_sizes, int n_in,
                              void* d_out, int out_size)
{
    const float* preds = (const float*)d_in[0];  // [4, 512, 16, 512]
    const float* gts   = (const float*)d_in[1];  // [4, 16, 512, 512]
    float* out = (float*)d_out;

    dim3 grid(CPB, B);                           // (18, 16) = 288 blocks, one wave
    minloss_fused<<<grid, 256>>>(preds, gts, out);
}

// round 8
// speedup vs baseline: 1.0167x; 1.0167x over previous
#include <cuda_runtime.h>
#include <cuda_bf16.h>
#include <math.h>

// Problem constants
constexpr int S = 4;
constexpr int T = 512;
constexpr int B = 16;
constexpr int D = 512;

constexpr int RPAIRS = T / 2;          // 256 t-row pairs per batch
constexpr int CPB    = 27;             // block slots per batch
constexpr int NBLOCKS = CPB * B;       // 432 ~= 148 SMs * occ 3, one wave
constexpr int NACC   = 16;             // 16 squared distances (sp*4+sg)

using u64 = unsigned long long;

// Deterministic scratch: per-(batch, block-slot) partial accumulators.
__device__ float g_part[B][CPB][NACC];
__device__ int   g_done = 0;

__device__ __forceinline__ void fma2(u64& acc, u64 a, u64 b) {
    asm("fma.rn.f32x2 %0, %1, %2, %0;" : "+l"(acc) : "l"(a), "l"(b));
}
__device__ __forceinline__ u64 add2(u64 a, u64 b) {
    u64 r;
    asm("add.rn.f32x2 %0, %1, %2;" : "=l"(r) : "l"(a), "l"(b));
    return r;
}
__device__ __forceinline__ u64 pack2(float lo, float hi) {
    u64 v;
    asm("mov.b64 %0, {%1, %2};" : "=l"(v) : "f"(lo), "f"(hi));
    return v;
}
__device__ __forceinline__ float unpack_sum(u64 v) {
    float lo, hi;
    asm("mov.b64 {%0, %1}, %2;" : "=f"(lo), "=f"(hi) : "l"(v));
    return lo + hi;
}

// ---------------------------------------------------------------------------
// Fused single-wave kernel, occupancy 3 (24 warps/SM).
// Block (cx, b): batch b, row pairs rp = cx, cx+27, ... (< 256).
// Thread layout: lane128 = tid & 127 spans D via float4; tid>>7 = row in pair.
// Accumulates the 16 squared distances DIRECTLY (no norms, no dots):
//   acc[sp][sg] += (p_sp - g_sg)^2   via sign-flip + add.f32x2 + fma.f32x2.
// ---------------------------------------------------------------------------
__global__ __launch_bounds__(256, 3) void minloss_fused(
    const float* __restrict__ preds,   // [S, T, B, D]
    const float* __restrict__ gts,     // [S, B, T, D]
    float* __restrict__ out)
{
    const int b    = blockIdx.y;
    const int cx   = blockIdx.x;
    const int tid  = threadIdx.x;
    const int lane128 = tid & 127;
    const int trow    = tid >> 7;      // 0 or 1: row within the pair

    const float4* pv = (const float4*)preds;   // D/4 = 128 vectors per row
    const float4* gv = (const float4*)gts;

    u64 acc[NACC];
#pragma unroll
    for (int i = 0; i < NACC; ++i) acc[i] = 0ull;   // == (0.f, 0.f)

    constexpr u64 SIGN2 = 0x8000000080000000ull;

    for (int rp = cx; rp < RPAIRS; rp += CPB) {
        const int t = 2 * rp + trow;
        float4 pr[4], gr[4];
#pragma unroll
        for (int s = 0; s < 4; ++s) {
            pr[s] = __ldcs(pv + ((size_t)(s * T + t) * B + b) * 128 + lane128);
            gr[s] = __ldcs(gv + ((size_t)(s * B + b) * T + t) * 128 + lane128);
        }
        u64 px[4][2], ng[4][2];
#pragma unroll
        for (int s = 0; s < 4; ++s) {
            px[s][0] = pack2(pr[s].x, pr[s].y);
            px[s][1] = pack2(pr[s].z, pr[s].w);
            ng[s][0] = pack2(gr[s].x, gr[s].y) ^ SIGN2;   // -g (packed sign flip)
            ng[s][1] = pack2(gr[s].z, gr[s].w) ^ SIGN2;
        }
#pragma unroll
        for (int sp = 0; sp < 4; ++sp) {
#pragma unroll
            for (int sg = 0; sg < 4; ++sg) {
                u64 d0 = add2(px[sp][0], ng[sg][0]);      // p - g
                fma2(acc[sp * 4 + sg], d0, d0);
                u64 d1 = add2(px[sp][1], ng[sg][1]);
                fma2(acc[sp * 4 + sg], d1, d1);
            }
        }
    }

    // Unpack + warp reduction
    float vals[NACC];
#pragma unroll
    for (int i = 0; i < NACC; ++i) {
        vals[i] = unpack_sum(acc[i]);
#pragma unroll
        for (int off = 16; off > 0; off >>= 1)
            vals[i] += __shfl_down_sync(0xffffffffu, vals[i], off);
    }

    __shared__ float sacc[8][NACC];
    const int warp = tid >> 5;
    const int lane = tid & 31;
    if (lane == 0) {
#pragma unroll
        for (int i = 0; i < NACC; ++i) sacc[warp][i] = vals[i];
    }
    __syncthreads();

    if (tid < NACC) {
        float a = 0.0f;
#pragma unroll
        for (int w = 0; w < 8; ++w) a += sacc[w][tid];
        g_part[b][cx][tid] = a;                       // deterministic overwrite
    }

    // ---- last-block ticket ----
    __threadfence();
    __syncthreads();
    __shared__ int s_last;
    if (tid == 0) {
        int ticket = atomicAdd(&g_done, 1);
        s_last = (ticket == NBLOCKS - 1);
    }
    __syncthreads();
    if (!s_last) return;

    // =========================== Phase B (last block) ===========================
    __threadfence();                                  // acquire

    __shared__ float s_final[B][NACC];

    // 8 warps; warp w reduces batches 2w and 2w+1. Lanes 0..15 own one acc idx.
#pragma unroll
    for (int k = 0; k < 2; ++k) {
        const int bb = warp * 2 + k;
        if (lane < NACC) {
            float a = 0.0f;
#pragma unroll
            for (int cc = 0; cc < CPB; ++cc)
                a += __ldcg(&g_part[bb][cc][lane]);   // L2, bypass stale L1
            s_final[bb][lane] = a;
        }
    }
    __syncthreads();

    __shared__ float batch_total[B];

    // 16 threads: one greedy matching per batch (first-occurrence argmin order).
    if (tid < B) {
        const float* a = s_final[tid];
        float dist[16];
#pragma unroll
        for (int i = 0; i < 16; ++i)
            dist[i] = sqrtf(fmaxf(a[i], 0.0f));       // d2 >= 0 by construction

        const float INF = __int_as_float(0x7f800000);
        float total = 0.0f;
#pragma unroll
        for (int it = 0; it < 4; ++it) {
            int   m    = 0;
            float best = dist[0];
#pragma unroll
            for (int k = 1; k < 16; ++k)
                if (dist[k] < best) { best = dist[k]; m = k; }
            total += best;
            const int r = m >> 2, cc = m & 3;
#pragma unroll
            for (int k = 0; k < 4; ++k) {
                dist[r * 4 + k]  = INF;
                dist[k * 4 + cc] = INF;
            }
        }
        batch_total[tid] = total;
    }
    __syncthreads();

    if (tid == 0) {
        float s = 0.0f;
#pragma unroll
        for (int bb = 0; bb < B; ++bb) s += batch_total[bb];
        out[0] = s;
        g_done = 0;                                   // reset for next graph replay
    }
}

extern "C" void kernel_launch(void* const* d_in, const int* in_sizes, int n_in,
                              void* d_out, int out_size)
{
    const float* preds = (const float*)d_in[0];  // [4, 512, 16, 512]
    const float* gts   = (const float*)d_in[1];  // [4, 16, 512, 512]
    float* out = (float*)d_out;

    dim3 grid(CPB, B);                           // (27, 16) = 432 blocks, one wave
    minloss_fused<<<grid, 256>>>(preds, gts, out);
}